// round 14
// baseline (speedup 1.0000x reference)
#include <cuda_runtime.h>
#include <math.h>

#define BB 32
#define TT 128
#define NFc 8
#define FF 128
#define NCC 1024
#define NCLS 1000
#define INV_N (1.0f/32768.0f)
#define GRID_MAIN 128

#define OUT_S 32000
#define OUT_N (OUT_S+262144)
#define OUT_D (OUT_N+262144)
#define OUT_H (OUT_D+262144)
#define OUT_AM (OUT_H+262144)

// ---------------- static device scratch ----------------
__device__ float g_xr[TT*BB*NCC];
__device__ float g_h[BB*NFc*NCC];
__device__ float4 g_partT[2][32][32];  // [parity][combo][b] = (S, S2, tag, pad)
__device__ float4 g_final[2][32];      // [parity][combo]    = (S, S2, tag, pad)

// ---------------- helpers ----------------
__device__ __forceinline__ float ldcg(const float* p){
    float v; asm volatile("ld.global.cg.f32 %0,[%1];":"=f"(v):"l"(p)); return v;
}
__device__ __forceinline__ float4 ldcg4(const float* p){
    float4 v; asm volatile("ld.global.cg.v4.f32 {%0,%1,%2,%3},[%4];"
        :"=f"(v.x),"=f"(v.y),"=f"(v.z),"=f"(v.w):"l"(p)); return v;
}
__device__ __forceinline__ void stcg4(float* p, float a,float b,float c,float d){
    asm volatile("st.global.cg.v4.f32 [%0],{%1,%2,%3,%4};"::"l"(p),"f"(a),"f"(b),"f"(c),"f"(d));
}
__device__ __forceinline__ void st_payload2(float* p, float a, float b){
    asm volatile("st.global.cg.v2.f32 [%0],{%1,%2};"::"l"(p),"f"(a),"f"(b):"memory");
}
__device__ __forceinline__ void st_rel(float* p, float v){
    asm volatile("st.release.gpu.global.f32 [%0],%1;"::"l"(p),"f"(v):"memory");
}
__device__ __forceinline__ float ld_acq(const float* p){
    float v; asm volatile("ld.acquire.gpu.global.f32 %0,[%1];":"=f"(v):"l"(p):"memory"); return v;
}
__device__ __forceinline__ float2 ld_payload2(const float* p){
    float2 v; asm volatile("ld.global.cg.v2.f32 {%0,%1},[%2];"
        :"=f"(v.x),"=f"(v.y):"l"(p):"memory"); return v;
}
__device__ __forceinline__ unsigned long long pk(float lo, float hi){
    unsigned long long r; asm("mov.b64 %0,{%1,%2};":"=l"(r):"f"(lo),"f"(hi)); return r;
}
__device__ __forceinline__ void up2(unsigned long long v, float& a, float& b){
    asm("mov.b64 {%0,%1},%2;":"=f"(a),"=f"(b):"l"(v));
}
__device__ __forceinline__ void fma2(unsigned long long& d, unsigned long long a, unsigned long long b){
    asm("fma.rn.f32x2 %0,%1,%2,%0;":"+l"(d):"l"(a),"l"(b));
}
__device__ __forceinline__ float ftanh(float x){
    float e = __expf(2.f*x);
    return 1.f - __fdividef(2.f, e + 1.f);
}
#define CLUSTER_SYNC() do { \
    asm volatile("barrier.cluster.arrive.aligned;" ::: "memory"); \
    asm volatile("barrier.cluster.wait.aligned;"   ::: "memory"); \
} while(0)

// ================= kernel 1: xr = x @ W^T (halves) =================
__global__ void __launch_bounds__(256) k_xr(const float* __restrict__ x,
                                            const float* __restrict__ w,
                                            int r_off){
    __shared__ float xs[128*34];
    __shared__ float ws[128*34];
    const int tid = threadIdx.x;
    const int r0 = blockIdx.x*32 + r_off;
    const int j0 = blockIdx.y*32;
    #pragma unroll
    for (int it=0; it<16; it++){
        int idx = tid + it*256;
        int rl = idx>>7, f = idx&127;
        int r = r0+rl, b = r&31, t = r>>5;
        xs[f*34+rl] = x[b*(TT*FF)+t*FF+f];
        ws[f*34+rl] = w[(j0+rl)*FF+f];
    }
    __syncthreads();
    const int rl0 = (tid>>4)*2, jl0 = (tid&15)*2;
    float a00=0,a01=0,a10=0,a11=0;
    #pragma unroll 8
    for (int f=0; f<128; f++){
        float2 xv = *(const float2*)&xs[f*34+rl0];
        float2 wv = *(const float2*)&ws[f*34+jl0];
        a00=fmaf(xv.x,wv.x,a00); a01=fmaf(xv.x,wv.y,a01);
        a10=fmaf(xv.y,wv.x,a10); a11=fmaf(xv.y,wv.y,a11);
    }
    int r = r0+rl0, j = j0+jl0;
    *(float2*)&g_xr[r*NCC+j]     = make_float2(a00,a01);
    *(float2*)&g_xr[(r+1)*NCC+j] = make_float2(a10,a11);
}

// ================= kernel 2: persistent recurrence =================
// CTA = (b, cpair): 2 channels x full 1024 j; 512 threads, thread = (cl, 4 j).
// cluster of 4 = the 4 cpairs of one b; peer h via L2 + cluster sync.
// BN stats: owner-reduction dataflow. Producers publish tagged partials;
// 32 owner warps (warp 15 of CTAs 0..31, combo = blockIdx.x) reduce the 32
// b-slots and publish one tagged final; consumers poll ONE uniform address.
__global__ void __launch_bounds__(512) __cluster_dims__(4,1,1) k_main(
    const float* __restrict__ in_s, const float* __restrict__ in_n,
    const float* __restrict__ in_d, const float* __restrict__ in_h,
    const float* __restrict__ in_am,
    const float* __restrict__ gw, const float* __restrict__ ggam, const float* __restrict__ gbet,
    const float* __restrict__ uw, const float* __restrict__ ugam, const float* __restrict__ ubet,
    const float* __restrict__ aw, const float* __restrict__ agam, const float* __restrict__ abet,
    const float* __restrict__ dw, const float* __restrict__ dgam, const float* __restrict__ dbet,
    float* __restrict__ out)
{
    __shared__ float  sxh[9*1032];        // row 0 = xr, rows 1..8 = h ch0..7; i = j+4
    __shared__ float2 wp2[2][3][9][5];    // local channels only
    __shared__ float  gbm[2][4][2];
    __shared__ float  smpart[16][8];
    __shared__ float2 smstat[2][4];

    const int tid = threadIdx.x;
    const int b = blockIdx.x >> 2, cpair = blockIdx.x & 3;
    const int cl = tid >> 8;              // 0..1 local channel
    const int jt = tid & 255;
    const int j0 = jt << 2;               // 4 j per thread
    const int c  = cpair*2 + cl;          // global channel
    const int base = (b*NFc + c)*NCC + j0;
    const int lane = tid & 31, wrp = tid >> 5;

    // weights (biases cancel under training-mode BN)
    for (int idx = tid; idx < 270; idx += 512){
        int cll = idx/135, r = idx%135, conv = r/45, r2 = r%45, ic = r2/5, k = r2%5;
        int cc = cpair*2 + cll;
        const float* W = (conv==0) ? gw : (conv==1) ? aw : dw;
        float wv = W[(cc*9+ic)*5+k];
        wp2[cll][conv][ic][k] = make_float2(wv, wv);
    }
    if (tid < 16){
        int cll = tid>>3, conv = (tid>>1)&3, isb = tid&1;
        int cc = cpair*2 + cll;
        const float* gm = (conv==0)?ggam:(conv==1)?agam:(conv==2)?dgam:ugam;
        const float* bt = (conv==0)?gbet:(conv==1)?abet:(conv==2)?dbet:ubet;
        gbm[cll][conv][isb] = isb ? bt[cc] : gm[cc];
    }
    if (tid < 9){
        int r = tid*1032;
        sxh[r]=0.f; sxh[r+1]=0.f; sxh[r+2]=0.f; sxh[r+3]=0.f;
        sxh[r+1028]=0.f; sxh[r+1029]=0.f; sxh[r+1030]=0.f; sxh[r+1031]=0.f;
    }
    unsigned long long uwp2[5];
    #pragma unroll
    for (int k=0;k<5;k++){ float wv = uw[c*5+k]; uwp2[k] = pk(wv, wv); }

    // stage xr(0)
    if (tid < 256)
        *(float4*)&sxh[4 + tid*4] = ldcg4(&g_xr[(0*BB+b)*NCC + tid*4]);

    // init state + h0 = h + tanh(s)
    float st_n[4], st_d[4], st_am[4], hv[4];
    #pragma unroll
    for (int p=0; p<4; p++){
        st_n[p]  = in_n[base+p];
        st_d[p]  = in_d[base+p];
        st_am[p] = in_am[base+p];
        hv[p]    = in_h[base+p] + ftanh(in_s[base+p]);
    }
    // own channel row -> local smem; L2 copy for cluster peers
    *(float4*)&sxh[(1+c)*1032 + 4 + j0] = make_float4(hv[0],hv[1],hv[2],hv[3]);
    stcg4(&g_h[base], hv[0],hv[1],hv[2],hv[3]);
    CLUSTER_SYNC();
    // stage the 6 peer channel rows: 1536 float4 slots, 3 per thread
    #pragma unroll
    for (int it = 0; it < 3; it++){
        int idx = tid + it*512;
        int row = idx >> 8, off = idx & 255;
        int pch = row + ((row >= cpair*2) ? 2 : 0);
        float4 r = ldcg4(&g_h[(b*NFc + pch)*NCC + off*4]);
        *(float4*)&sxh[(1+pch)*1032 + 4 + off*4] = r;
    }
    __syncthreads();

    for (int t = 0; t < TT; t++){
        const float tagf = (float)(t+1);
        // ---- convs (packed f32x2), 4 positions per thread ----
        unsigned long long AG[2],AA[2],AD[2],AU[2];
        AG[0]=AG[1]=AA[0]=AA[1]=AD[0]=AD[1]=AU[0]=AU[1]=0ull;
        #pragma unroll
        for (int ic = 0; ic < 9; ic++){
            const float* row = &sxh[ic*1032 + j0];
            float4 l0 = *(const float4*)(row);
            float4 l1 = *(const float4*)(row+4);
            float4 l2 = *(const float4*)(row+8);
            float L[12] = {l0.x,l0.y,l0.z,l0.w,l1.x,l1.y,l1.z,l1.w,l2.x,l2.y,l2.z,l2.w};
            unsigned long long vp[7];
            #pragma unroll
            for (int m=0;m<7;m++) vp[m] = pk(L[m+2], L[m+3]);
            #pragma unroll
            for (int k=0;k<5;k++){
                unsigned long long wg = *(const unsigned long long*)&wp2[cl][0][ic][k];
                unsigned long long wa = *(const unsigned long long*)&wp2[cl][1][ic][k];
                unsigned long long wd = *(const unsigned long long*)&wp2[cl][2][ic][k];
                fma2(AG[0], wg, vp[k]);   fma2(AG[1], wg, vp[k+2]);
                fma2(AA[0], wa, vp[k]);   fma2(AA[1], wa, vp[k+2]);
                fma2(AD[0], wd, vp[k]);   fma2(AD[1], wd, vp[k+2]);
            }
            if (ic == 0){
                #pragma unroll
                for (int k=0;k<5;k++){
                    fma2(AU[0], uwp2[k], vp[k]); fma2(AU[1], uwp2[k], vp[k+2]);
                }
            }
        }
        float ag[4],aa[4],ad[4],au[4];
        up2(AG[0],ag[0],ag[1]); up2(AG[1],ag[2],ag[3]);
        up2(AA[0],aa[0],aa[1]); up2(AA[1],aa[2],aa[3]);
        up2(AD[0],ad[0],ad[1]); up2(AD[1],ad[2],ad[3]);
        up2(AU[0],au[0],au[1]); up2(AU[1],au[2],au[3]);

        // ---- BN partials: thread -> warp -> CTA ----
        float s8[8] = {0,0,0,0,0,0,0,0};
        #pragma unroll
        for (int p=0;p<4;p++){
            s8[0]+=ag[p]; s8[1]=fmaf(ag[p],ag[p],s8[1]);
            s8[2]+=aa[p]; s8[3]=fmaf(aa[p],aa[p],s8[3]);
            s8[4]+=ad[p]; s8[5]=fmaf(ad[p],ad[p],s8[5]);
            s8[6]+=au[p]; s8[7]=fmaf(au[p],au[p],s8[7]);
        }
        #pragma unroll
        for (int q=0;q<8;q++){
            #pragma unroll
            for (int off=16; off; off>>=1)
                s8[q] += __shfl_xor_sync(0xffffffffu, s8[q], off);
        }
        if (lane == 0){
            #pragma unroll
            for (int q=0;q<8;q++) smpart[wrp][q] = s8[q];
        }
        __syncthreads();   // conv reads of sxh done CTA-wide; smpart ready

        if (tid < 8){
            // producer: combine 8 warps per (cll,conv); publish tagged partial
            int cll = tid>>2, conv = tid&3;
            float S = 0.f, S2 = 0.f;
            #pragma unroll
            for (int i=0;i<8;i++){
                S  += smpart[cll*8+i][conv*2+0];
                S2 += smpart[cll*8+i][conv*2+1];
            }
            int combo = (cpair*2+cll)*4 + conv;
            float* slot = (float*)&g_partT[t&1][combo][b];
            st_payload2(slot, S, S2);
            st_rel(slot+2, tagf);
        } else if (tid >= 256 && tid < 480 && t+1 < TT){
            // stage xr(t+1); conv(t) reads done (syncthreads above)
            for (int i = tid-256; i < 256; i += 224)
                *(float4*)&sxh[4 + i*4] = ldcg4(&g_xr[((t+1)*BB+b)*NCC + i*4]);
        } else if (wrp == 15 && blockIdx.x < 32){
            // owner: reduce 32 b-partials of combo=blockIdx.x, publish final
            int combo = blockIdx.x;
            const float* slot = (const float*)&g_partT[t&1][combo][lane];
            float tg;
            do { tg = ld_acq(slot+2); } while (tg != tagf);
            float2 v = ld_payload2(slot);
            float S = v.x, S2 = v.y;
            #pragma unroll
            for (int off=16; off; off>>=1){
                S  += __shfl_xor_sync(0xffffffffu, S,  off);
                S2 += __shfl_xor_sync(0xffffffffu, S2, off);
            }
            if (lane == 0){
                float* fs = (float*)&g_final[t&1][combo];
                st_payload2(fs, S, S2);
                st_rel(fs+2, tagf);
            }
        }

        // ---- consumers: warps 0..7 poll one uniform final slot each ----
        if (wrp < 8){
            int cll = wrp>>2, conv = wrp&3;
            int combo = (cpair*2+cll)*4 + conv;
            const float* fs = (const float*)&g_final[t&1][combo];
            float tg;
            do { tg = ld_acq(fs+2); } while (tg != tagf);
            if (lane == 0){
                float2 v = ld_payload2(fs);
                float mean = v.x * INV_N;
                float var  = fmaf(-mean, mean, v.y * INV_N);
                float sc = gbm[cll][conv][0] * rsqrtf(var + 1e-5f);
                smstat[cll][conv] = make_float2(sc, fmaf(-mean, sc, gbm[cll][conv][1]));
            }
        }
        __syncthreads();
        const float2 gss = smstat[cl][0];
        const float2 ass = smstat[cl][1];
        const float2 dss = smstat[cl][2];
        const float2 uss = smstat[cl][3];

        // ---- state update ----
        #pragma unroll
        for (int p = 0; p < 4; p++){
            float g   = fmaf(ag[p], gss.x, gss.y);
            float a   = fmaf(aa[p], ass.x, ass.y);
            float dcv = fmaf(ad[p], dss.x, dss.y);
            float u   = fmaf(au[p], uss.x, uss.y);
            float dec = __fdividef(1.f, 1.f + __expf(-dcv));
            float ed  = __expf(-dec);
            float z   = u * ftanh(g);
            float anew = fmaxf(st_am[p]*ed, a);
            float k1 = __expf(st_am[p] - anew - dec);   // = ed * exp(am - anew)
            float e2 = __expf(a - anew);
            st_n[p]  = fmaf(st_n[p], k1, z*e2);
            st_d[p]  = fmaf(st_d[p], k1, e2);
            st_am[p] = anew;
            hv[p] = ftanh(__fdividef(st_n[p], st_d[p]));
        }

        if (t+1 < TT){
            // own row local; peer copy via L2. Safe to overwrite g_h(t-1):
            // consuming final(t) implies every CTA stored partial(t), which
            // implies conv(t) done, which implies its restage reads of
            // g_h(t-1) (end of step t-1) completed.
            *(float4*)&sxh[(1+c)*1032 + 4 + j0] = make_float4(hv[0],hv[1],hv[2],hv[3]);
            stcg4(&g_h[base], hv[0],hv[1],hv[2],hv[3]);
            CLUSTER_SYNC();   // release own h; acquire peers' h
            #pragma unroll
            for (int it = 0; it < 3; it++){
                int idx = tid + it*512;
                int row = idx >> 8, off = idx & 255;
                int pch = row + ((row >= cpair*2) ? 2 : 0);
                float4 r = ldcg4(&g_h[(b*NFc + pch)*NCC + off*4]);
                *(float4*)&sxh[(1+pch)*1032 + 4 + off*4] = r;
            }
            __syncthreads();
        }
    }

    // ---- final outputs (+ g_h for classifier) ----
    stcg4(&g_h[base], hv[0],hv[1],hv[2],hv[3]);
    *(float4*)&out[OUT_N  + base] = make_float4(st_n[0],st_n[1],st_n[2],st_n[3]);
    *(float4*)&out[OUT_D  + base] = make_float4(st_d[0],st_d[1],st_d[2],st_d[3]);
    *(float4*)&out[OUT_H  + base] = make_float4(hv[0],hv[1],hv[2],hv[3]);
    *(float4*)&out[OUT_AM + base] = make_float4(st_am[0],st_am[1],st_am[2],st_am[3]);
}

// ================= kernel 3: classifier =================
__global__ void __launch_bounds__(256) k_out(const float* __restrict__ ow,
                                             const float* __restrict__ ob,
                                             float* __restrict__ out){
    const int wrp = threadIdx.x >> 5, lane = threadIdx.x & 31;
    const int cls = blockIdx.x*8 + wrp;
    float acc[32];
    #pragma unroll
    for (int b=0;b<32;b++) acc[b]=0.f;
    const float* wr = &ow[(long)cls*8192];
    for (int k = lane; k < 8192; k += 32){
        float wv = wr[k];
        #pragma unroll
        for (int b=0;b<32;b++) acc[b] = fmaf(g_h[b*8192+k], wv, acc[b]);
    }
    float res = 0.f;
    #pragma unroll
    for (int b=0;b<32;b++){
        float v = acc[b];
        #pragma unroll
        for (int off=16; off; off>>=1) v += __shfl_xor_sync(0xffffffffu, v, off);
        if (lane == b) res = v;
    }
    out[lane*NCLS + cls] = res + ob[cls];
}

// ================= kernel 4: tag reset (runs FIRST each replay) =================
__global__ void __launch_bounds__(512) k_rst(){
    float4* p = (float4*)g_partT;
    for (int i = threadIdx.x; i < 2*32*32; i += 512)
        p[i] = make_float4(0.f, 0.f, 0.f, 0.f);
    float4* q = (float4*)g_final;
    if (threadIdx.x < 64)
        q[threadIdx.x] = make_float4(0.f, 0.f, 0.f, 0.f);
}

// ================= launch =================
extern "C" void kernel_launch(void* const* d_in, const int* in_sizes, int n_in,
                              void* d_out, int out_size){
    const float* x    = (const float*)d_in[0];
    const float* s    = (const float*)d_in[1];
    const float* n_   = (const float*)d_in[2];
    const float* d_   = (const float*)d_in[3];
    const float* h_   = (const float*)d_in[4];
    const float* am   = (const float*)d_in[5];
    const float* xrw  = (const float*)d_in[6];
    const float* gw   = (const float*)d_in[7];
    const float* ggam = (const float*)d_in[9];
    const float* gbet = (const float*)d_in[10];
    const float* uw   = (const float*)d_in[11];
    const float* ugam = (const float*)d_in[13];
    const float* ubet = (const float*)d_in[14];
    const float* aw   = (const float*)d_in[15];
    const float* agam = (const float*)d_in[17];
    const float* abet = (const float*)d_in[18];
    const float* dw   = (const float*)d_in[19];
    const float* dgam = (const float*)d_in[21];
    const float* dbet = (const float*)d_in[22];
    const float* ow   = (const float*)d_in[23];
    const float* ob   = (const float*)d_in[24];
    float* out = (float*)d_out;

    k_rst<<<1, 512>>>();
    k_xr<<<dim3(64, NCC/32), 256>>>(x, xrw, 0);
    k_xr<<<dim3(64, NCC/32), 256>>>(x, xrw, 2048);
    k_main<<<GRID_MAIN, 512>>>(s, n_, d_, h_, am,
                               gw, ggam, gbet, uw, ugam, ubet,
                               aw, agam, abet, dw, dgam, dbet, out);
    k_out<<<125, 256>>>(ow, ob, out);
    cudaMemcpyAsync(out + OUT_S, s, 262144*sizeof(float),
                    cudaMemcpyDeviceToDevice, 0);
}

// round 15
// speedup vs baseline: 1.3554x; 1.3554x over previous
#include <cuda_runtime.h>
#include <math.h>

#define BB 32
#define TT 128
#define NFc 8
#define FF 128
#define NCC 1024
#define NCLS 1000
#define INV_N (1.0f/32768.0f)
#define GRID_MAIN 128

#define OUT_S 32000
#define OUT_N (OUT_S+262144)
#define OUT_D (OUT_N+262144)
#define OUT_H (OUT_D+262144)
#define OUT_AM (OUT_H+262144)

// ---------------- static device scratch ----------------
__device__ float g_xr[TT*BB*NCC];
__device__ float g_h[BB*NFc*NCC];
__device__ float g_part[2][64][32];   // [parity][(c*4+conv)*2+stat][b]
__device__ unsigned g_cnt;            // monotonic; k_rst zeros first

// ---------------- helpers ----------------
__device__ __forceinline__ float ldcg(const float* p){
    float v; asm volatile("ld.global.cg.f32 %0,[%1];":"=f"(v):"l"(p)); return v;
}
__device__ __forceinline__ float4 ldcg4(const float* p){
    float4 v; asm volatile("ld.global.cg.v4.f32 {%0,%1,%2,%3},[%4];"
        :"=f"(v.x),"=f"(v.y),"=f"(v.z),"=f"(v.w):"l"(p)); return v;
}
__device__ __forceinline__ void stcg(float* p, float v){
    asm volatile("st.global.cg.f32 [%0],%1;"::"l"(p),"f"(v));
}
__device__ __forceinline__ void stcg4(float* p, float a,float b,float c,float d){
    asm volatile("st.global.cg.v4.f32 [%0],{%1,%2,%3,%4};"::"l"(p),"f"(a),"f"(b),"f"(c),"f"(d));
}
__device__ __forceinline__ unsigned ldacq(const unsigned* p){
    unsigned v; asm volatile("ld.acquire.gpu.b32 %0,[%1];":"=r"(v):"l"(p):"memory"); return v;
}
__device__ __forceinline__ unsigned long long pk(float lo, float hi){
    unsigned long long r; asm("mov.b64 %0,{%1,%2};":"=l"(r):"f"(lo),"f"(hi)); return r;
}
__device__ __forceinline__ void up2(unsigned long long v, float& a, float& b){
    asm("mov.b64 {%0,%1},%2;":"=f"(a),"=f"(b):"l"(v));
}
__device__ __forceinline__ void fma2(unsigned long long& d, unsigned long long a, unsigned long long b){
    asm("fma.rn.f32x2 %0,%1,%2,%0;":"+l"(d):"l"(a),"l"(b));
}
__device__ __forceinline__ float ftanh(float x){
    float e = __expf(2.f*x);
    return 1.f - __fdividef(2.f, e + 1.f);
}
#define CLUSTER_ARRIVE() asm volatile("barrier.cluster.arrive.aligned;" ::: "memory")
#define CLUSTER_WAIT()   asm volatile("barrier.cluster.wait.aligned;"   ::: "memory")

// one-hop monotonic grid barrier
__device__ __forceinline__ void grid_bar(unsigned target){
    __syncthreads();
    if (threadIdx.x == 0){
        asm volatile("red.release.gpu.add.u32 [%0],%1;"::"l"(&g_cnt),"r"(1u):"memory");
        while ((int)(ldacq(&g_cnt) - target) < 0){}
    }
    __syncthreads();
}

// conv accumulator over one smem row
struct Acc { unsigned long long g[2], a[2], d[2], u[2]; };
__device__ __forceinline__ void acc_zero(Acc& A){
    A.g[0]=A.g[1]=A.a[0]=A.a[1]=A.d[0]=A.d[1]=A.u[0]=A.u[1]=0ull;
}
__device__ __forceinline__ void acc_row(Acc& A, const float* sxh, int ic, int j0,
                                        const float2 (*wpc)[9][5],
                                        const unsigned long long* uwp2, bool do_u){
    const float* row = &sxh[ic*1032 + j0];
    float4 l0 = *(const float4*)(row);
    float4 l1 = *(const float4*)(row+4);
    float4 l2 = *(const float4*)(row+8);
    float L[12] = {l0.x,l0.y,l0.z,l0.w,l1.x,l1.y,l1.z,l1.w,l2.x,l2.y,l2.z,l2.w};
    unsigned long long vp[7];
    #pragma unroll
    for (int m=0;m<7;m++) vp[m] = pk(L[m+2], L[m+3]);
    #pragma unroll
    for (int k=0;k<5;k++){
        unsigned long long wg = *(const unsigned long long*)&wpc[0][ic][k];
        unsigned long long wa = *(const unsigned long long*)&wpc[1][ic][k];
        unsigned long long wd = *(const unsigned long long*)&wpc[2][ic][k];
        fma2(A.g[0], wg, vp[k]);   fma2(A.g[1], wg, vp[k+2]);
        fma2(A.a[0], wa, vp[k]);   fma2(A.a[1], wa, vp[k+2]);
        fma2(A.d[0], wd, vp[k]);   fma2(A.d[1], wd, vp[k+2]);
    }
    if (do_u){
        #pragma unroll
        for (int k=0;k<5;k++){
            fma2(A.u[0], uwp2[k], vp[k]); fma2(A.u[1], uwp2[k], vp[k+2]);
        }
    }
}

// ================= kernel 1: xr = x @ W^T (halves) =================
__global__ void __launch_bounds__(256) k_xr(const float* __restrict__ x,
                                            const float* __restrict__ w,
                                            int r_off){
    __shared__ float xs[128*34];
    __shared__ float ws[128*34];
    const int tid = threadIdx.x;
    const int r0 = blockIdx.x*32 + r_off;
    const int j0 = blockIdx.y*32;
    #pragma unroll
    for (int it=0; it<16; it++){
        int idx = tid + it*256;
        int rl = idx>>7, f = idx&127;
        int r = r0+rl, b = r&31, t = r>>5;
        xs[f*34+rl] = x[b*(TT*FF)+t*FF+f];
        ws[f*34+rl] = w[(j0+rl)*FF+f];
    }
    __syncthreads();
    const int rl0 = (tid>>4)*2, jl0 = (tid&15)*2;
    float a00=0,a01=0,a10=0,a11=0;
    #pragma unroll 8
    for (int f=0; f<128; f++){
        float2 xv = *(const float2*)&xs[f*34+rl0];
        float2 wv = *(const float2*)&ws[f*34+jl0];
        a00=fmaf(xv.x,wv.x,a00); a01=fmaf(xv.x,wv.y,a01);
        a10=fmaf(xv.y,wv.x,a10); a11=fmaf(xv.y,wv.y,a11);
    }
    int r = r0+rl0, j = j0+jl0;
    *(float2*)&g_xr[r*NCC+j]     = make_float2(a00,a01);
    *(float2*)&g_xr[(r+1)*NCC+j] = make_float2(a10,a11);
}

// ================= kernel 2: persistent recurrence =================
// CTA = (b, cpair): 2 channels x full 1024 j; 512 threads, thread = (cl, 4 j).
// cluster of 4 = the 4 cpairs of one b; peer h via L2 + split cluster barrier.
// Conv software-pipelined across the cluster barrier: rows {xr, own0, own1}
// pre-accumulated before the cluster wait; 6 peer rows finished at loop top.
__global__ void __launch_bounds__(512) __cluster_dims__(4,1,1) k_main(
    const float* __restrict__ in_s, const float* __restrict__ in_n,
    const float* __restrict__ in_d, const float* __restrict__ in_h,
    const float* __restrict__ in_am,
    const float* __restrict__ gw, const float* __restrict__ ggam, const float* __restrict__ gbet,
    const float* __restrict__ uw, const float* __restrict__ ugam, const float* __restrict__ ubet,
    const float* __restrict__ aw, const float* __restrict__ agam, const float* __restrict__ abet,
    const float* __restrict__ dw, const float* __restrict__ dgam, const float* __restrict__ dbet,
    float* __restrict__ out)
{
    __shared__ float  sxh[9*1032];        // row 0 = xr, rows 1..8 = h ch0..7; i = j+4
    __shared__ float2 wp2[2][3][9][5];    // local channels only
    __shared__ float  gbm[2][4][2];
    __shared__ float  smpart[16][8];
    __shared__ float2 smstat[2][4];

    const int tid = threadIdx.x;
    const int b = blockIdx.x >> 2, cpair = blockIdx.x & 3;
    const int cl = tid >> 8;              // 0..1 local channel
    const int jt = tid & 255;
    const int j0 = jt << 2;               // 4 j per thread
    const int c  = cpair*2 + cl;          // global channel
    const int base = (b*NFc + c)*NCC + j0;
    const int lane = tid & 31, wrp = tid >> 5;
    const int own0 = 1 + cpair*2, own1 = 2 + cpair*2;   // smem row indices

    // weights (biases cancel under training-mode BN)
    for (int idx = tid; idx < 270; idx += 512){
        int cll = idx/135, r = idx%135, conv = r/45, r2 = r%45, ic = r2/5, k = r2%5;
        int cc = cpair*2 + cll;
        const float* W = (conv==0) ? gw : (conv==1) ? aw : dw;
        float wv = W[(cc*9+ic)*5+k];
        wp2[cll][conv][ic][k] = make_float2(wv, wv);
    }
    if (tid < 16){
        int cll = tid>>3, conv = (tid>>1)&3, isb = tid&1;
        int cc = cpair*2 + cll;
        const float* gm = (conv==0)?ggam:(conv==1)?agam:(conv==2)?dgam:ugam;
        const float* bt = (conv==0)?gbet:(conv==1)?abet:(conv==2)?dbet:ubet;
        gbm[cll][conv][isb] = isb ? bt[cc] : gm[cc];
    }
    if (tid < 9){
        int r = tid*1032;
        sxh[r]=0.f; sxh[r+1]=0.f; sxh[r+2]=0.f; sxh[r+3]=0.f;
        sxh[r+1028]=0.f; sxh[r+1029]=0.f; sxh[r+1030]=0.f; sxh[r+1031]=0.f;
    }
    unsigned long long uwp2[5];
    #pragma unroll
    for (int k=0;k<5;k++){ float wv = uw[c*5+k]; uwp2[k] = pk(wv, wv); }
    const float2 (*wpc)[9][5] = wp2[cl];

    // stage xr(0)
    if (tid < 256)
        *(float4*)&sxh[4 + tid*4] = ldcg4(&g_xr[(0*BB+b)*NCC + tid*4]);

    // init state + h0 = h + tanh(s)
    float st_n[4], st_d[4], st_am[4], hv[4];
    #pragma unroll
    for (int p=0; p<4; p++){
        st_n[p]  = in_n[base+p];
        st_d[p]  = in_d[base+p];
        st_am[p] = in_am[base+p];
        hv[p]    = in_h[base+p] + ftanh(in_s[base+p]);
    }
    // own channel row -> local smem; L2 copy for cluster peers
    *(float4*)&sxh[(1+c)*1032 + 4 + j0] = make_float4(hv[0],hv[1],hv[2],hv[3]);
    stcg4(&g_h[base], hv[0],hv[1],hv[2],hv[3]);
    CLUSTER_ARRIVE();
    __syncthreads();

    // pre-accumulate conv(0): xr row + own 2 rows
    Acc A;
    acc_zero(A);
    acc_row(A, sxh, 0,    j0, wpc, uwp2, true);
    acc_row(A, sxh, own0, j0, wpc, uwp2, false);
    acc_row(A, sxh, own1, j0, wpc, uwp2, false);

    CLUSTER_WAIT();
    // stage the 6 peer channel rows: 1536 float4 slots, 3 per thread
    #pragma unroll
    for (int it = 0; it < 3; it++){
        int idx = tid + it*512;
        int row = idx >> 8, off = idx & 255;
        int pch = row + ((row >= cpair*2) ? 2 : 0);
        float4 r = ldcg4(&g_h[(b*NFc + pch)*NCC + off*4]);
        *(float4*)&sxh[(1+pch)*1032 + 4 + off*4] = r;
    }
    __syncthreads();

    unsigned nb = 0;

    for (int t = 0; t < TT; t++){
        // ---- finish conv(t): 6 peer rows ----
        #pragma unroll
        for (int q = 0; q < 6; q++){
            int pp = q >> 1;
            pp += (pp >= cpair);
            int ic = 1 + pp*2 + (q & 1);
            acc_row(A, sxh, ic, j0, wpc, uwp2, false);
        }
        float ag[4],aa[4],ad[4],au[4];
        up2(A.g[0],ag[0],ag[1]); up2(A.g[1],ag[2],ag[3]);
        up2(A.a[0],aa[0],aa[1]); up2(A.a[1],aa[2],aa[3]);
        up2(A.d[0],ad[0],ad[1]); up2(A.d[1],ad[2],ad[3]);
        up2(A.u[0],au[0],au[1]); up2(A.u[1],au[2],au[3]);

        // ---- BN partials: thread -> warp -> CTA -> global ----
        float s8[8] = {0,0,0,0,0,0,0,0};
        #pragma unroll
        for (int p=0;p<4;p++){
            s8[0]+=ag[p]; s8[1]=fmaf(ag[p],ag[p],s8[1]);
            s8[2]+=aa[p]; s8[3]=fmaf(aa[p],aa[p],s8[3]);
            s8[4]+=ad[p]; s8[5]=fmaf(ad[p],ad[p],s8[5]);
            s8[6]+=au[p]; s8[7]=fmaf(au[p],au[p],s8[7]);
        }
        #pragma unroll
        for (int q=0;q<8;q++){
            #pragma unroll
            for (int off=16; off; off>>=1)
                s8[q] += __shfl_xor_sync(0xffffffffu, s8[q], off);
        }
        if (lane == 0){
            #pragma unroll
            for (int q=0;q<8;q++) smpart[wrp][q] = s8[q];
        }
        __syncthreads();   // conv reads of sxh done CTA-wide; smpart ready
        if (tid < 16){
            int cll = tid>>3, q = tid&7;
            float v = 0.f;
            #pragma unroll
            for (int i=0;i<8;i++) v += smpart[cll*8+i][q];
            int conv = q>>1, stat = q&1;
            int cc = cpair*2 + cll;
            stcg(&g_part[t&1][(cc*4+conv)*2+stat][b], v);
        } else if (tid >= 256 && t+1 < TT){
            int tt = tid - 256;   // stage xr(t+1); conv(t) reads done
            *(float4*)&sxh[4 + tt*4] = ldcg4(&g_xr[((t+1)*BB+b)*NCC + tt*4]);
        }

        grid_bar((++nb) * GRID_MAIN);

        // ---- gather stats: warps 0..7 -> (cl = w>>2, conv = w&3) ----
        if (wrp < 8){
            int cll = wrp>>2, conv = wrp&3;
            int cc = cpair*2 + cll;
            float S  = ldcg(&g_part[t&1][(cc*4+conv)*2+0][lane]);
            float S2 = ldcg(&g_part[t&1][(cc*4+conv)*2+1][lane]);
            #pragma unroll
            for (int off=16; off; off>>=1){
                S  += __shfl_xor_sync(0xffffffffu, S,  off);
                S2 += __shfl_xor_sync(0xffffffffu, S2, off);
            }
            if (lane == 0){
                float mean = S * INV_N;
                float var  = fmaf(-mean, mean, S2 * INV_N);
                float sc = gbm[cll][conv][0] * rsqrtf(var + 1e-5f);
                smstat[cll][conv] = make_float2(sc, fmaf(-mean, sc, gbm[cll][conv][1]));
            }
        }
        __syncthreads();
        const float2 gss = smstat[cl][0];
        const float2 ass = smstat[cl][1];
        const float2 dss = smstat[cl][2];
        const float2 uss = smstat[cl][3];

        // ---- state update ----
        #pragma unroll
        for (int p = 0; p < 4; p++){
            float g   = fmaf(ag[p], gss.x, gss.y);
            float a   = fmaf(aa[p], ass.x, ass.y);
            float dcv = fmaf(ad[p], dss.x, dss.y);
            float u   = fmaf(au[p], uss.x, uss.y);
            float dec = __fdividef(1.f, 1.f + __expf(-dcv));
            float ed  = __expf(-dec);
            float z   = u * ftanh(g);
            float anew = fmaxf(st_am[p]*ed, a);
            float k1 = __expf(st_am[p] - anew - dec);   // = ed * exp(am - anew)
            float e2 = __expf(a - anew);
            st_n[p]  = fmaf(st_n[p], k1, z*e2);
            st_d[p]  = fmaf(st_d[p], k1, e2);
            st_am[p] = anew;
            hv[p] = ftanh(__fdividef(st_n[p], st_d[p]));
        }

        if (t+1 < TT){
            // own row local; peer copy via L2 (grid_bar above guarantees
            // conv(t) finished grid-wide, so rows are dead).
            *(float4*)&sxh[(1+c)*1032 + 4 + j0] = make_float4(hv[0],hv[1],hv[2],hv[3]);
            stcg4(&g_h[base], hv[0],hv[1],hv[2],hv[3]);
            CLUSTER_ARRIVE();            // release own h (non-blocking)
            __syncthreads();             // own rows complete CTA-wide in smem

            // pre-accumulate conv(t+1) over locally-available rows
            acc_zero(A);
            acc_row(A, sxh, 0,    j0, wpc, uwp2, true);
            acc_row(A, sxh, own0, j0, wpc, uwp2, false);
            acc_row(A, sxh, own1, j0, wpc, uwp2, false);

            CLUSTER_WAIT();              // acquire peers' h
            #pragma unroll
            for (int it = 0; it < 3; it++){
                int idx = tid + it*512;
                int row = idx >> 8, off = idx & 255;
                int pch = row + ((row >= cpair*2) ? 2 : 0);
                float4 r = ldcg4(&g_h[(b*NFc + pch)*NCC + off*4]);
                *(float4*)&sxh[(1+pch)*1032 + 4 + off*4] = r;
            }
            __syncthreads();
        }
    }

    // ---- final outputs (+ g_h for classifier) ----
    stcg4(&g_h[base], hv[0],hv[1],hv[2],hv[3]);
    *(float4*)&out[OUT_N  + base] = make_float4(st_n[0],st_n[1],st_n[2],st_n[3]);
    *(float4*)&out[OUT_D  + base] = make_float4(st_d[0],st_d[1],st_d[2],st_d[3]);
    *(float4*)&out[OUT_H  + base] = make_float4(hv[0],hv[1],hv[2],hv[3]);
    *(float4*)&out[OUT_AM + base] = make_float4(st_am[0],st_am[1],st_am[2],st_am[3]);
}

// ================= kernel 3: classifier =================
__global__ void __launch_bounds__(256) k_out(const float* __restrict__ ow,
                                             const float* __restrict__ ob,
                                             float* __restrict__ out){
    const int wrp = threadIdx.x >> 5, lane = threadIdx.x & 31;
    const int cls = blockIdx.x*8 + wrp;
    float acc[32];
    #pragma unroll
    for (int b=0;b<32;b++) acc[b]=0.f;
    const float* wr = &ow[(long)cls*8192];
    for (int k = lane; k < 8192; k += 32){
        float wv = wr[k];
        #pragma unroll
        for (int b=0;b<32;b++) acc[b] = fmaf(g_h[b*8192+k], wv, acc[b]);
    }
    float res = 0.f;
    #pragma unroll
    for (int b=0;b<32;b++){
        float v = acc[b];
        #pragma unroll
        for (int off=16; off; off>>=1) v += __shfl_xor_sync(0xffffffffu, v, off);
        if (lane == b) res = v;
    }
    out[lane*NCLS + cls] = res + ob[cls];
}

// ================= kernel 4: barrier counter reset (runs FIRST) =================
__global__ void k_rst(){ g_cnt = 0u; }

// ================= launch =================
extern "C" void kernel_launch(void* const* d_in, const int* in_sizes, int n_in,
                              void* d_out, int out_size){
    const float* x    = (const float*)d_in[0];
    const float* s    = (const float*)d_in[1];
    const float* n_   = (const float*)d_in[2];
    const float* d_   = (const float*)d_in[3];
    const float* h_   = (const float*)d_in[4];
    const float* am   = (const float*)d_in[5];
    const float* xrw  = (const float*)d_in[6];
    const float* gw   = (const float*)d_in[7];
    const float* ggam = (const float*)d_in[9];
    const float* gbet = (const float*)d_in[10];
    const float* uw   = (const float*)d_in[11];
    const float* ugam = (const float*)d_in[13];
    const float* ubet = (const float*)d_in[14];
    const float* aw   = (const float*)d_in[15];
    const float* agam = (const float*)d_in[17];
    const float* abet = (const float*)d_in[18];
    const float* dw   = (const float*)d_in[19];
    const float* dgam = (const float*)d_in[21];
    const float* dbet = (const float*)d_in[22];
    const float* ow   = (const float*)d_in[23];
    const float* ob   = (const float*)d_in[24];
    float* out = (float*)d_out;

    k_rst<<<1, 1>>>();
    k_xr<<<dim3(64, NCC/32), 256>>>(x, xrw, 0);
    k_xr<<<dim3(64, NCC/32), 256>>>(x, xrw, 2048);
    k_main<<<GRID_MAIN, 512>>>(s, n_, d_, h_, am,
                               gw, ggam, gbet, uw, ugam, ubet,
                               aw, agam, abet, dw, dgam, dbet, out);
    k_out<<<125, 256>>>(ow, ob, out);
    cudaMemcpyAsync(out + OUT_S, s, 262144*sizeof(float),
                    cudaMemcpyDeviceToDevice, 0);
}

// round 16
// speedup vs baseline: 1.9566x; 1.4435x over previous
#include <cuda_runtime.h>
#include <math.h>

#define BB 32
#define TT 128
#define NFc 8
#define FF 128
#define NCC 1024
#define NCLS 1000
#define INV_N (1.0f/32768.0f)
#define GRID_MAIN 128

#define OUT_S 32000
#define OUT_N (OUT_S+262144)
#define OUT_D (OUT_N+262144)
#define OUT_H (OUT_D+262144)
#define OUT_AM (OUT_H+262144)

// ---------------- static device scratch ----------------
__device__ float g_xr[TT*BB*NCC];
__device__ float g_h[BB*NFc*NCC];
__device__ float g_part[2][64][32];   // [parity][(c*4+conv)*2+stat][b]
__device__ unsigned g_cnt;            // monotonic; k_rst zeros first

// ---------------- helpers ----------------
__device__ __forceinline__ float ldcg(const float* p){
    float v; asm volatile("ld.global.cg.f32 %0,[%1];":"=f"(v):"l"(p)); return v;
}
__device__ __forceinline__ float4 ldcg4(const float* p){
    float4 v; asm volatile("ld.global.cg.v4.f32 {%0,%1,%2,%3},[%4];"
        :"=f"(v.x),"=f"(v.y),"=f"(v.z),"=f"(v.w):"l"(p)); return v;
}
__device__ __forceinline__ void stcg(float* p, float v){
    asm volatile("st.global.cg.f32 [%0],%1;"::"l"(p),"f"(v));
}
__device__ __forceinline__ void stcg4(float* p, float a,float b,float c,float d){
    asm volatile("st.global.cg.v4.f32 [%0],{%1,%2,%3,%4};"::"l"(p),"f"(a),"f"(b),"f"(c),"f"(d));
}
__device__ __forceinline__ unsigned ldacq(const unsigned* p){
    unsigned v; asm volatile("ld.acquire.gpu.b32 %0,[%1];":"=r"(v):"l"(p):"memory"); return v;
}
__device__ __forceinline__ unsigned long long pk(float lo, float hi){
    unsigned long long r; asm("mov.b64 %0,{%1,%2};":"=l"(r):"f"(lo),"f"(hi)); return r;
}
__device__ __forceinline__ void up2(unsigned long long v, float& a, float& b){
    asm("mov.b64 {%0,%1},%2;":"=f"(a),"=f"(b):"l"(v));
}
__device__ __forceinline__ void fma2(unsigned long long& d, unsigned long long a, unsigned long long b){
    asm("fma.rn.f32x2 %0,%1,%2,%0;":"+l"(d):"l"(a),"l"(b));
}
__device__ __forceinline__ float ftanh(float x){
    float e = __expf(2.f*x);
    return 1.f - __fdividef(2.f, e + 1.f);
}
#define CLUSTER_ARRIVE() asm volatile("barrier.cluster.arrive.aligned;" ::: "memory")
#define CLUSTER_WAIT()   asm volatile("barrier.cluster.wait.aligned;"   ::: "memory")

// one-hop monotonic grid barrier
__device__ __forceinline__ void grid_bar(unsigned target){
    __syncthreads();
    if (threadIdx.x == 0){
        asm volatile("red.release.gpu.add.u32 [%0],%1;"::"l"(&g_cnt),"r"(1u):"memory");
        while ((int)(ldacq(&g_cnt) - target) < 0){}
    }
    __syncthreads();
}

// conv accumulator over one smem row
struct Acc { unsigned long long g[2], a[2], d[2], u[2]; };
__device__ __forceinline__ void acc_zero(Acc& A){
    A.g[0]=A.g[1]=A.a[0]=A.a[1]=A.d[0]=A.d[1]=A.u[0]=A.u[1]=0ull;
}
__device__ __forceinline__ void acc_row(Acc& A, const float* sxh, int ic, int j0,
                                        const float2 (*wpc)[9][5],
                                        const unsigned long long* uwp2, bool do_u){
    const float* row = &sxh[ic*1032 + j0];
    float4 l0 = *(const float4*)(row);
    float4 l1 = *(const float4*)(row+4);
    float4 l2 = *(const float4*)(row+8);
    float L[12] = {l0.x,l0.y,l0.z,l0.w,l1.x,l1.y,l1.z,l1.w,l2.x,l2.y,l2.z,l2.w};
    unsigned long long vp[7];
    #pragma unroll
    for (int m=0;m<7;m++) vp[m] = pk(L[m+2], L[m+3]);
    #pragma unroll
    for (int k=0;k<5;k++){
        unsigned long long wg = *(const unsigned long long*)&wpc[0][ic][k];
        unsigned long long wa = *(const unsigned long long*)&wpc[1][ic][k];
        unsigned long long wd = *(const unsigned long long*)&wpc[2][ic][k];
        fma2(A.g[0], wg, vp[k]);   fma2(A.g[1], wg, vp[k+2]);
        fma2(A.a[0], wa, vp[k]);   fma2(A.a[1], wa, vp[k+2]);
        fma2(A.d[0], wd, vp[k]);   fma2(A.d[1], wd, vp[k+2]);
    }
    if (do_u){
        #pragma unroll
        for (int k=0;k<5;k++){
            fma2(A.u[0], uwp2[k], vp[k]); fma2(A.u[1], uwp2[k], vp[k+2]);
        }
    }
}

// ================= kernel: everything fused =================
// Prologue: CTA bx computes xr[t=bx][all b][all j] (GEMM, smem overlay on sxh).
// Core: R15 recurrence (CTA = (b,cpair), 512 thr, pipelined cluster barrier).
// Epilogue: classifier, 2 warps per class (k-split), vectorized LDG.128.
__global__ void __launch_bounds__(512) __cluster_dims__(4,1,1) k_main(
    const float* __restrict__ x, const float* __restrict__ xrw,
    const float* __restrict__ in_s, const float* __restrict__ in_n,
    const float* __restrict__ in_d, const float* __restrict__ in_h,
    const float* __restrict__ in_am,
    const float* __restrict__ gw, const float* __restrict__ ggam, const float* __restrict__ gbet,
    const float* __restrict__ uw, const float* __restrict__ ugam, const float* __restrict__ ubet,
    const float* __restrict__ aw, const float* __restrict__ agam, const float* __restrict__ abet,
    const float* __restrict__ dw, const float* __restrict__ dgam, const float* __restrict__ dbet,
    const float* __restrict__ ow, const float* __restrict__ ob,
    float* __restrict__ out)
{
    __shared__ float  sxh[9*1032];        // row 0 = xr, rows 1..8 = h; ALSO gemm/cls scratch
    __shared__ float2 wp2[2][3][9][5];
    __shared__ float  gbm[2][4][2];
    __shared__ float  smpart[16][8];
    __shared__ float2 smstat[2][4];

    const int tid = threadIdx.x;
    const int bx = blockIdx.x;
    const int b = bx >> 2, cpair = bx & 3;
    const int cl = tid >> 8;
    const int jt = tid & 255;
    const int j0 = jt << 2;
    const int c  = cpair*2 + cl;
    const int base = (b*NFc + c)*NCC + j0;
    const int lane = tid & 31, wrp = tid >> 5;
    const int own0 = 1 + cpair*2, own1 = 2 + cpair*2;

    unsigned nb = 0;

    // ======== PROLOGUE: xr[t=bx][rb][j] for rb=0..31, j=0..1023 ========
    {
        float* xs  = sxh;          // [128][34] : xs[f*34+rb]
        float* wsm = sxh + 4352;   // [128][34] : wsm[f*34+jl]
        // load x tile once: x[rb][t=bx][f]
        for (int idx = tid; idx < 4096; idx += 512){
            int rb = idx >> 7, f = idx & 127;
            xs[f*34 + rb] = x[rb*(TT*FF) + bx*FF + f];
        }
        const int jl = tid & 31, rl2 = tid >> 5;   // rows 2*rl2, 2*rl2+1
        for (int it = 0; it < 32; it++){
            int jb = it*32;
            __syncthreads();
            for (int idx = tid; idx < 4096; idx += 512){
                int jj = idx >> 7, f = idx & 127;
                wsm[f*34 + jj] = xrw[(jb + jj)*FF + f];
            }
            __syncthreads();
            float a0 = 0.f, a1 = 0.f;
            #pragma unroll 8
            for (int f = 0; f < 128; f++){
                float2 xv = *(const float2*)&xs[f*34 + 2*rl2];
                float wv = wsm[f*34 + jl];
                a0 = fmaf(xv.x, wv, a0);
                a1 = fmaf(xv.y, wv, a1);
            }
            int r = bx*32 + 2*rl2;
            stcg(&g_xr[r*NCC + jb + jl], a0);
            stcg(&g_xr[(r+1)*NCC + jb + jl], a1);
        }
    }
    grid_bar((++nb) * GRID_MAIN);   // all xr visible

    // ======== load weights / BN params, zero halos ========
    for (int idx = tid; idx < 270; idx += 512){
        int cll = idx/135, r = idx%135, conv = r/45, r2 = r%45, ic = r2/5, k = r2%5;
        int cc = cpair*2 + cll;
        const float* W = (conv==0) ? gw : (conv==1) ? aw : dw;
        float wv = W[(cc*9+ic)*5+k];
        wp2[cll][conv][ic][k] = make_float2(wv, wv);
    }
    if (tid < 16){
        int cll = tid>>3, conv = (tid>>1)&3, isb = tid&1;
        int cc = cpair*2 + cll;
        const float* gm = (conv==0)?ggam:(conv==1)?agam:(conv==2)?dgam:ugam;
        const float* bt = (conv==0)?gbet:(conv==1)?abet:(conv==2)?dbet:ubet;
        gbm[cll][conv][isb] = isb ? bt[cc] : gm[cc];
    }
    if (tid < 9){
        int r = tid*1032;
        sxh[r]=0.f; sxh[r+1]=0.f; sxh[r+2]=0.f; sxh[r+3]=0.f;
        sxh[r+1028]=0.f; sxh[r+1029]=0.f; sxh[r+1030]=0.f; sxh[r+1031]=0.f;
    }
    unsigned long long uwp2[5];
    #pragma unroll
    for (int k=0;k<5;k++){ float wv = uw[c*5+k]; uwp2[k] = pk(wv, wv); }
    const float2 (*wpc)[9][5] = wp2[cl];
    __syncthreads();

    // stage xr(0)
    if (tid < 256)
        *(float4*)&sxh[4 + tid*4] = ldcg4(&g_xr[(0*BB+b)*NCC + tid*4]);

    // init state + h0 = h + tanh(s)
    float st_n[4], st_d[4], st_am[4], hv[4];
    #pragma unroll
    for (int p=0; p<4; p++){
        st_n[p]  = in_n[base+p];
        st_d[p]  = in_d[base+p];
        st_am[p] = in_am[base+p];
        hv[p]    = in_h[base+p] + ftanh(in_s[base+p]);
    }
    *(float4*)&sxh[(1+c)*1032 + 4 + j0] = make_float4(hv[0],hv[1],hv[2],hv[3]);
    stcg4(&g_h[base], hv[0],hv[1],hv[2],hv[3]);
    CLUSTER_ARRIVE();
    __syncthreads();

    Acc A;
    acc_zero(A);
    acc_row(A, sxh, 0,    j0, wpc, uwp2, true);
    acc_row(A, sxh, own0, j0, wpc, uwp2, false);
    acc_row(A, sxh, own1, j0, wpc, uwp2, false);

    CLUSTER_WAIT();
    #pragma unroll
    for (int it = 0; it < 3; it++){
        int idx = tid + it*512;
        int row = idx >> 8, off = idx & 255;
        int pch = row + ((row >= cpair*2) ? 2 : 0);
        float4 r = ldcg4(&g_h[(b*NFc + pch)*NCC + off*4]);
        *(float4*)&sxh[(1+pch)*1032 + 4 + off*4] = r;
    }
    __syncthreads();

    // ======== RECURRENCE ========
    for (int t = 0; t < TT; t++){
        #pragma unroll
        for (int q = 0; q < 6; q++){
            int pp = q >> 1;
            pp += (pp >= cpair);
            int ic = 1 + pp*2 + (q & 1);
            acc_row(A, sxh, ic, j0, wpc, uwp2, false);
        }
        float ag[4],aa[4],ad[4],au[4];
        up2(A.g[0],ag[0],ag[1]); up2(A.g[1],ag[2],ag[3]);
        up2(A.a[0],aa[0],aa[1]); up2(A.a[1],aa[2],aa[3]);
        up2(A.d[0],ad[0],ad[1]); up2(A.d[1],ad[2],ad[3]);
        up2(A.u[0],au[0],au[1]); up2(A.u[1],au[2],au[3]);

        float s8[8] = {0,0,0,0,0,0,0,0};
        #pragma unroll
        for (int p=0;p<4;p++){
            s8[0]+=ag[p]; s8[1]=fmaf(ag[p],ag[p],s8[1]);
            s8[2]+=aa[p]; s8[3]=fmaf(aa[p],aa[p],s8[3]);
            s8[4]+=ad[p]; s8[5]=fmaf(ad[p],ad[p],s8[5]);
            s8[6]+=au[p]; s8[7]=fmaf(au[p],au[p],s8[7]);
        }
        #pragma unroll
        for (int q=0;q<8;q++){
            #pragma unroll
            for (int off=16; off; off>>=1)
                s8[q] += __shfl_xor_sync(0xffffffffu, s8[q], off);
        }
        if (lane == 0){
            #pragma unroll
            for (int q=0;q<8;q++) smpart[wrp][q] = s8[q];
        }
        __syncthreads();
        if (tid < 16){
            int cll = tid>>3, q = tid&7;
            float v = 0.f;
            #pragma unroll
            for (int i=0;i<8;i++) v += smpart[cll*8+i][q];
            int conv = q>>1, stat = q&1;
            int cc = cpair*2 + cll;
            stcg(&g_part[t&1][(cc*4+conv)*2+stat][b], v);
        } else if (tid >= 256 && t+1 < TT){
            int tt = tid - 256;
            *(float4*)&sxh[4 + tt*4] = ldcg4(&g_xr[((t+1)*BB+b)*NCC + tt*4]);
        }

        grid_bar((++nb) * GRID_MAIN);

        if (wrp < 8){
            int cll = wrp>>2, conv = wrp&3;
            int cc = cpair*2 + cll;
            float S  = ldcg(&g_part[t&1][(cc*4+conv)*2+0][lane]);
            float S2 = ldcg(&g_part[t&1][(cc*4+conv)*2+1][lane]);
            #pragma unroll
            for (int off=16; off; off>>=1){
                S  += __shfl_xor_sync(0xffffffffu, S,  off);
                S2 += __shfl_xor_sync(0xffffffffu, S2, off);
            }
            if (lane == 0){
                float mean = S * INV_N;
                float var  = fmaf(-mean, mean, S2 * INV_N);
                float sc = gbm[cll][conv][0] * rsqrtf(var + 1e-5f);
                smstat[cll][conv] = make_float2(sc, fmaf(-mean, sc, gbm[cll][conv][1]));
            }
        }
        __syncthreads();
        const float2 gss = smstat[cl][0];
        const float2 ass = smstat[cl][1];
        const float2 dss = smstat[cl][2];
        const float2 uss = smstat[cl][3];

        #pragma unroll
        for (int p = 0; p < 4; p++){
            float g   = fmaf(ag[p], gss.x, gss.y);
            float a   = fmaf(aa[p], ass.x, ass.y);
            float dcv = fmaf(ad[p], dss.x, dss.y);
            float u   = fmaf(au[p], uss.x, uss.y);
            float dec = __fdividef(1.f, 1.f + __expf(-dcv));
            float ed  = __expf(-dec);
            float z   = u * ftanh(g);
            float anew = fmaxf(st_am[p]*ed, a);
            float k1 = __expf(st_am[p] - anew - dec);
            float e2 = __expf(a - anew);
            st_n[p]  = fmaf(st_n[p], k1, z*e2);
            st_d[p]  = fmaf(st_d[p], k1, e2);
            st_am[p] = anew;
            hv[p] = ftanh(__fdividef(st_n[p], st_d[p]));
        }

        if (t+1 < TT){
            *(float4*)&sxh[(1+c)*1032 + 4 + j0] = make_float4(hv[0],hv[1],hv[2],hv[3]);
            stcg4(&g_h[base], hv[0],hv[1],hv[2],hv[3]);
            CLUSTER_ARRIVE();
            __syncthreads();

            acc_zero(A);
            acc_row(A, sxh, 0,    j0, wpc, uwp2, true);
            acc_row(A, sxh, own0, j0, wpc, uwp2, false);
            acc_row(A, sxh, own1, j0, wpc, uwp2, false);

            CLUSTER_WAIT();
            #pragma unroll
            for (int it = 0; it < 3; it++){
                int idx = tid + it*512;
                int row = idx >> 8, off = idx & 255;
                int pch = row + ((row >= cpair*2) ? 2 : 0);
                float4 r = ldcg4(&g_h[(b*NFc + pch)*NCC + off*4]);
                *(float4*)&sxh[(1+pch)*1032 + 4 + off*4] = r;
            }
            __syncthreads();
        }
    }

    // ---- final state outputs ----
    stcg4(&g_h[base], hv[0],hv[1],hv[2],hv[3]);
    *(float4*)&out[OUT_N  + base] = make_float4(st_n[0],st_n[1],st_n[2],st_n[3]);
    *(float4*)&out[OUT_D  + base] = make_float4(st_d[0],st_d[1],st_d[2],st_d[3]);
    *(float4*)&out[OUT_H  + base] = make_float4(hv[0],hv[1],hv[2],hv[3]);
    *(float4*)&out[OUT_AM + base] = make_float4(st_am[0],st_am[1],st_am[2],st_am[3]);

    grid_bar((++nb) * GRID_MAIN);   // all final g_h visible

    // ======== EPILOGUE: classifier (2 warps per class, k-split) ========
    {
        float* smcls = sxh;   // [8][2][32]
        int cls = bx*8 + (wrp >> 1);
        int khalf = wrp & 1;
        if (cls < NCLS){
            float acc[32];
            #pragma unroll
            for (int q=0;q<32;q++) acc[q]=0.f;
            const float* wr = ow + (long)cls*8192 + khalf*4096;
            const float* hb = g_h + khalf*4096;
            for (int it = 0; it < 32; it++){
                int k = lane*4 + it*128;
                float4 wv = ldcg4(&wr[k]);
                #pragma unroll
                for (int q=0;q<32;q++){
                    float4 h4 = ldcg4(&hb[q*8192 + k]);
                    acc[q] = fmaf(h4.x, wv.x, acc[q]);
                    acc[q] = fmaf(h4.y, wv.y, acc[q]);
                    acc[q] = fmaf(h4.z, wv.z, acc[q]);
                    acc[q] = fmaf(h4.w, wv.w, acc[q]);
                }
            }
            float res = 0.f;
            #pragma unroll
            for (int q=0;q<32;q++){
                float v = acc[q];
                #pragma unroll
                for (int off=16; off; off>>=1) v += __shfl_xor_sync(0xffffffffu, v, off);
                if (lane == q) res = v;
            }
            smcls[(wrp>>1)*64 + khalf*32 + lane] = res;
        }
        __syncthreads();
        if (tid < 256){
            int cl8 = tid>>5, bb = tid&31;
            int cls2 = bx*8 + cl8;
            if (cls2 < NCLS)
                out[bb*NCLS + cls2] = smcls[cl8*64 + bb] + smcls[cl8*64 + 32 + bb] + ob[cls2];
        }
    }
}

// ================= kernel: barrier counter reset (runs FIRST) =================
__global__ void k_rst(){ g_cnt = 0u; }

// ================= launch =================
extern "C" void kernel_launch(void* const* d_in, const int* in_sizes, int n_in,
                              void* d_out, int out_size){
    const float* x    = (const float*)d_in[0];
    const float* s    = (const float*)d_in[1];
    const float* n_   = (const float*)d_in[2];
    const float* d_   = (const float*)d_in[3];
    const float* h_   = (const float*)d_in[4];
    const float* am   = (const float*)d_in[5];
    const float* xrw  = (const float*)d_in[6];
    const float* gw   = (const float*)d_in[7];
    const float* ggam = (const float*)d_in[9];
    const float* gbet = (const float*)d_in[10];
    const float* uw   = (const float*)d_in[11];
    const float* ugam = (const float*)d_in[13];
    const float* ubet = (const float*)d_in[14];
    const float* aw   = (const float*)d_in[15];
    const float* agam = (const float*)d_in[17];
    const float* abet = (const float*)d_in[18];
    const float* dw   = (const float*)d_in[19];
    const float* dgam = (const float*)d_in[21];
    const float* dbet = (const float*)d_in[22];
    const float* ow   = (const float*)d_in[23];
    const float* ob   = (const float*)d_in[24];
    float* out = (float*)d_out;

    k_rst<<<1, 1>>>();
    k_main<<<GRID_MAIN, 512>>>(x, xrw, s, n_, d_, h_, am,
                               gw, ggam, gbet, uw, ugam, ubet,
                               aw, agam, abet, dw, dgam, dbet,
                               ow, ob, out);
    cudaMemcpyAsync(out + OUT_S, s, 262144*sizeof(float),
                    cudaMemcpyDeviceToDevice, 0);
}